// round 2
// baseline (speedup 1.0000x reference)
#include <cuda_runtime.h>
#include <cstdint>

#define TSTEPS 300
#define HIDN   512
#define EMBD   300
#define G4     2048      // 4*HIDN

// ---------------- scratch (static __device__, no allocs) ----------------
__device__ __align__(16) float g_pre[TSTEPS * G4]; // input-side gates (+biases)
__device__ __align__(16) float g_h[2][HIDN];       // double-buffered hidden state
__device__ __align__(16) float g_c[HIDN];          // cell state (owner-only access)

__device__ __forceinline__ float sigm(float x) { return 1.f / (1.f + __expf(-x)); }
__device__ __forceinline__ float tanh_f(float x) {
    // overflow-safe: tanh(x) = sign(x) * (1 - 2/(exp(2|x|)+1))
    float e = __expf(2.f * fabsf(x));
    float r = 1.f - 2.f / (e + 1.f);
    return copysignf(r, x);
}

// ================= Phase 1: pre[t][row] = W_ih @ emb[x[t]] + b_ih + b_hh ==========
// grid (128, 19), block 256.  Block covers 16 rows x 16 timesteps; K=300 loop.
__global__ void pre_kernel(const int* __restrict__ x,
                           const float* __restrict__ emb,
                           const float* __restrict__ W_ih,
                           const float* __restrict__ b_ih,
                           const float* __restrict__ b_hh,
                           const float* __restrict__ h0,
                           const float* __restrict__ c0)
{
    __shared__ float E[16][301];   // stride 301 -> conflict-free column reads
    const int tB = blockIdx.y * 16;
    const int rB = blockIdx.x * 16;

    // gather 16 embedding rows into smem
    for (int idx = threadIdx.x; idx < 16 * EMBD; idx += 256) {
        int tt = idx / EMBD, k = idx % EMBD;
        int t = tB + tt;
        E[tt][k] = (t < TSTEPS) ? emb[(size_t)x[t] * EMBD + k] : 0.f;
    }
    __syncthreads();

    const int t_local = threadIdx.x & 15;
    const int r_local = threadIdx.x >> 4;
    const int r = rB + r_local;
    const int t = tB + t_local;

    const float* wr = W_ih + (size_t)r * EMBD;
    float a0 = 0.f, a1 = 0.f, a2 = 0.f, a3 = 0.f;
    #pragma unroll 4
    for (int k = 0; k < EMBD; k += 4) {
        a0 = fmaf(wr[k + 0], E[t_local][k + 0], a0);
        a1 = fmaf(wr[k + 1], E[t_local][k + 1], a1);
        a2 = fmaf(wr[k + 2], E[t_local][k + 2], a2);
        a3 = fmaf(wr[k + 3], E[t_local][k + 3], a3);
    }
    if (t < TSTEPS)
        g_pre[(size_t)t * G4 + r] = (a0 + a1) + (a2 + a3) + b_ih[r] + b_hh[r];

    // one block also initializes h/c state
    if (blockIdx.x == 0 && blockIdx.y == 0) {
        for (int i = threadIdx.x; i < HIDN; i += 256) {
            g_h[0][i] = h0[i];
            g_c[i]    = c0[i];
        }
    }
}

// ================= Phase 2: one LSTM step per kernel (kernel boundary = barrier) ===
// grid 64, block 256.  CTA c owns hidden units [8c, 8c+8) -> 32 gate rows.
// Thread t: row-in-CTA rr = t/8 (gate = rr/8, unit = rr%8), chunk s = t%8 (64 MACs).
__global__ void __launch_bounds__(256, 4)
step_kernel(const float* __restrict__ W_hh, int step)
{
    const int c  = blockIdx.x;
    const int t  = threadIdx.x;
    const int rr = t >> 3;                 // 0..31
    const int s  = t & 7;                  // 0..7
    const int gate = rr >> 3;              // 0..3 (i,f,g,o)
    const int unit = (c << 3) + (rr & 7);  // global hidden unit
    const int grow = gate * HIDN + unit;   // global gate row

    __shared__ __align__(16) float hs[8 * 68];  // 8 segments of 64 h-values, stride 68
    __shared__ float gsm[32];

    // stage h[step&1] into bank-staggered smem segments
    const float* __restrict__ hsrc = g_h[step & 1];
    if (t < 128) {
        float4 v = *reinterpret_cast<const float4*>(hsrc + 4 * t);
        int seg = t >> 4;
        int off = (t * 4) & 63;
        *reinterpret_cast<float4*>(&hs[seg * 68 + off]) = v;
    }
    float prev = 0.f;
    if (s == 0) prev = g_pre[(size_t)step * G4 + grow];
    __syncthreads();

    // 64-MAC partial dot: W from L2 (float4), h from conflict-free smem
    const float4* __restrict__ wp4 =
        reinterpret_cast<const float4*>(W_hh + (size_t)grow * HIDN + s * 64);
    const float4* hp4 = reinterpret_cast<const float4*>(&hs[s * 68]);
    float a0 = 0.f, a1 = 0.f, a2 = 0.f, a3 = 0.f;
    #pragma unroll
    for (int i = 0; i < 16; ++i) {
        float4 wv = wp4[i];
        float4 h4 = hp4[i];
        a0 = fmaf(wv.x, h4.x, a0);
        a1 = fmaf(wv.y, h4.y, a1);
        a2 = fmaf(wv.z, h4.z, a2);
        a3 = fmaf(wv.w, h4.w, a3);
    }
    float part = (a0 + a1) + (a2 + a3);
    part += __shfl_down_sync(0xffffffffu, part, 4, 8);
    part += __shfl_down_sync(0xffffffffu, part, 2, 8);
    part += __shfl_down_sync(0xffffffffu, part, 1, 8);
    if (s == 0) gsm[rr] = part + prev;
    __syncthreads();

    // cell update for the 8 owned units; publish h to the other buffer
    if (t < 8) {
        int u = (c << 3) + t;
        float gi = gsm[t], gf = gsm[8 + t], gg = gsm[16 + t], go = gsm[24 + t];
        float i_ = sigm(gi);
        float f_ = sigm(gf);
        float g_ = tanh_f(gg);
        float o_ = sigm(go);
        float cn = fmaf(f_, g_c[u], i_ * g_);
        g_c[u] = cn;
        g_h[(step + 1) & 1][u] = o_ * tanh_f(cn);
    }
}

// ================= Phase 3: out[0] = sigmoid(h . fc_w + b); copy h, c ==============
__global__ void fc_kernel(const float* __restrict__ fc_w,
                          const float* __restrict__ fc_b,
                          float* __restrict__ out)
{
    const int t = threadIdx.x;             // 512 threads
    __shared__ float red[16];

    const float* hfin = g_h[TSTEPS & 1];   // TSTEPS=300 even -> buffer 0
    float hv = hfin[t];
    float cv = g_c[t];
    out[1 + t]   = hv;
    out[513 + t] = cv;

    float p = hv * fc_w[t];
    #pragma unroll
    for (int o = 16; o > 0; o >>= 1) p += __shfl_down_sync(0xffffffffu, p, o);
    if ((t & 31) == 0) red[t >> 5] = p;
    __syncthreads();
    if (t == 0) {
        float acc = fc_b[0];
        #pragma unroll
        for (int i = 0; i < 16; ++i) acc += red[i];
        out[0] = sigm(acc);
    }
}

// ================= launch =================
extern "C" void kernel_launch(void* const* d_in, const int* in_sizes, int n_in,
                              void* d_out, int out_size)
{
    const int*   x     = (const int*)  d_in[0];
    const float* h0    = (const float*)d_in[1];
    const float* c0    = (const float*)d_in[2];
    const float* emb   = (const float*)d_in[3];
    const float* W_ih  = (const float*)d_in[4];
    const float* W_hh  = (const float*)d_in[5];
    const float* b_ih  = (const float*)d_in[6];
    const float* b_hh  = (const float*)d_in[7];
    const float* fc_w  = (const float*)d_in[8];
    const float* fc_b  = (const float*)d_in[9];
    float* out = (float*)d_out;

    dim3 pgrid(G4 / 16, (TSTEPS + 15) / 16);   // 128 x 19
    pre_kernel<<<pgrid, 256>>>(x, emb, W_ih, b_ih, b_hh, h0, c0);

    for (int step = 0; step < TSTEPS; ++step)
        step_kernel<<<64, 256>>>(W_hh, step);

    fc_kernel<<<1, 512>>>(fc_w, fc_b, out);
}

// round 4
// speedup vs baseline: 1.8303x; 1.8303x over previous
#include <cuda_runtime.h>
#include <cuda/atomic>
#include <cstdint>

#define TSTEPS 300
#define HIDN   512
#define EMBD   300
#define G4     2048      // 4*HIDN
#define NCTA   32
#define TPB    512
#define SPIN_GUARD (1 << 20)

// ---------------- scratch (static __device__, no allocs) ----------------
__device__ __align__(16) float g_pre[TSTEPS * G4]; // input-side gates (+biases)
__device__ __align__(16) float g_h[2][HIDN];       // double-buffered hidden state
__device__ __align__(16) int   g_bar[4];           // [0] = monotonic barrier counter

using dev_atomic_int = cuda::atomic_ref<int, cuda::thread_scope_device>;
using dev_atomic_f32 = cuda::atomic_ref<float, cuda::thread_scope_device>;

__device__ __forceinline__ float sigm(float x) { return 1.f / (1.f + __expf(-x)); }
__device__ __forceinline__ float tanh_f(float x) {
    // overflow-safe: tanh(x) = sign(x) * (1 - 2/(exp(2|x|)+1))
    float e = __expf(2.f * fabsf(x));
    float r = 1.f - 2.f / (e + 1.f);
    return copysignf(r, x);
}

// ================= Phase 1: pre[t][row] = W_ih @ emb[x[t]] + b_ih + b_hh ==========
// grid (128, 19), block 256.  Block covers 16 rows x 16 timesteps; K=300 loop.
__global__ void pre_kernel(const int* __restrict__ x,
                           const float* __restrict__ emb,
                           const float* __restrict__ W_ih,
                           const float* __restrict__ b_ih,
                           const float* __restrict__ b_hh,
                           const float* __restrict__ h0)
{
    __shared__ float E[16][301];   // stride 301 -> conflict-free column reads
    const int tB = blockIdx.y * 16;
    const int rB = blockIdx.x * 16;

    for (int idx = threadIdx.x; idx < 16 * EMBD; idx += 256) {
        int tt = idx / EMBD, k = idx % EMBD;
        int t = tB + tt;
        E[tt][k] = (t < TSTEPS) ? emb[(size_t)x[t] * EMBD + k] : 0.f;
    }
    __syncthreads();

    const int t_local = threadIdx.x & 15;
    const int r_local = threadIdx.x >> 4;
    const int r = rB + r_local;
    const int t = tB + t_local;

    const float* wr = W_ih + (size_t)r * EMBD;
    float a0 = 0.f, a1 = 0.f, a2 = 0.f, a3 = 0.f;
    #pragma unroll 4
    for (int k = 0; k < EMBD; k += 4) {
        a0 = fmaf(wr[k + 0], E[t_local][k + 0], a0);
        a1 = fmaf(wr[k + 1], E[t_local][k + 1], a1);
        a2 = fmaf(wr[k + 2], E[t_local][k + 2], a2);
        a3 = fmaf(wr[k + 3], E[t_local][k + 3], a3);
    }
    if (t < TSTEPS)
        g_pre[(size_t)t * G4 + r] = (a0 + a1) + (a2 + a3) + b_ih[r] + b_hh[r];

    // one block also resets the barrier counter and seeds h
    if (blockIdx.x == 0 && blockIdx.y == 0) {
        if (threadIdx.x == 0) g_bar[0] = 0;
        for (int i = threadIdx.x; i < HIDN; i += 256) g_h[0][i] = h0[i];
    }
}

// ================= Phase 2: persistent recurrence =================
// 32 CTAs x 512 threads.  CTA c owns hidden units [16c,16c+16) -> 64 gate rows.
// Thread t: row rr = t>>3 (gate = rr>>4, unit = rr&15), h-chunk s = t&7 (64 MACs).
// W_hh slice lives in registers for all 300 steps.
// Cross-CTA sync: monotonic counter, release-add / acquire-load (libcu++);
// h exchanged via relaxed device-scope atomics -> fully morally-strong chain.
__global__ void __launch_bounds__(TPB, 1)
lstm_persist(const float* __restrict__ W_hh,
             const float* __restrict__ c0,
             const float* __restrict__ fc_w,
             const float* __restrict__ fc_b,
             float* __restrict__ out)
{
    const int c  = blockIdx.x;
    const int t  = threadIdx.x;
    const int rr = t >> 3;                 // 0..63
    const int s  = t & 7;                  // 0..7
    const int gate = rr >> 4;              // 0..3 (i,f,g,o)
    const int unit = (c << 4) + (rr & 15); // global hidden unit
    const int grow = gate * HIDN + unit;   // global gate row

    __shared__ __align__(16) float hs[8 * 68];  // 8 segments x 64 h-values, stride 68
    __shared__ float gsm[64];
    __shared__ float red[16];

    dev_atomic_int bar(g_bar[0]);

    // ---- load W_hh slice into registers (kept for all 300 steps) ----
    float w[64];
    {
        const float4* wrow =
            reinterpret_cast<const float4*>(W_hh + (size_t)grow * HIDN + s * 64);
        #pragma unroll
        for (int i = 0; i < 16; ++i) {
            float4 v = wrow[i];
            w[4 * i + 0] = v.x; w[4 * i + 1] = v.y;
            w[4 * i + 2] = v.z; w[4 * i + 3] = v.w;
        }
    }

    float cv = 0.f, hv = 0.f;              // state for the 16 owner threads
    if (t < 16) cv = c0[(c << 4) + t];

    for (int step = 0; step < TSTEPS; ++step) {
        // ---- wait: everyone finished step-1  (counter >= NCTA*step) ----
        if (t == 0) {
            const int target = NCTA * step;
            int guard = 0;
            while (bar.load(cuda::memory_order_acquire) < target) {
                if (++guard > SPIN_GUARD) break;   // bounded: never hang the bench
            }
        }
        __syncthreads();                    // extends t0's acquire to the CTA

        // ---- stage h[buf] into bank-staggered smem (relaxed atomic loads) ----
        const int buf = step & 1;
        {
            dev_atomic_f32 href(((float*)g_h[buf])[t]);
            hs[(t >> 6) * 68 + (t & 63)] = href.load(cuda::memory_order_relaxed);
        }
        float prev = 0.f;
        if (s == 0) prev = g_pre[(size_t)step * G4 + grow];
        __syncthreads();

        // ---- 64-MAC partial dot: W in regs, h from conflict-free smem ----
        float a0 = 0.f, a1 = 0.f, a2 = 0.f, a3 = 0.f;
        const float4* hp4 = reinterpret_cast<const float4*>(&hs[s * 68]);
        #pragma unroll
        for (int i = 0; i < 16; ++i) {
            float4 h4 = hp4[i];
            a0 = fmaf(w[4 * i + 0], h4.x, a0);
            a1 = fmaf(w[4 * i + 1], h4.y, a1);
            a2 = fmaf(w[4 * i + 2], h4.z, a2);
            a3 = fmaf(w[4 * i + 3], h4.w, a3);
        }
        float part = (a0 + a1) + (a2 + a3);
        part += __shfl_down_sync(0xffffffffu, part, 4, 8);
        part += __shfl_down_sync(0xffffffffu, part, 2, 8);
        part += __shfl_down_sync(0xffffffffu, part, 1, 8);
        if (s == 0) gsm[rr] = part + prev;
        __syncthreads();

        // ---- cell update for the 16 owned units; publish h ----
        if (t < 16) {
            float gi = gsm[t], gf = gsm[16 + t], gg = gsm[32 + t], go = gsm[48 + t];
            float i_ = sigm(gi);
            float f_ = sigm(gf);
            float g_ = tanh_f(gg);
            float o_ = sigm(go);
            float cn = fmaf(f_, cv, i_ * g_);
            cv = cn;
            hv = o_ * tanh_f(cn);
            dev_atomic_f32 hdst(((float*)g_h[buf ^ 1])[(c << 4) + t]);
            hdst.store(hv, cuda::memory_order_relaxed);
        }
        __syncthreads();                    // owners' stores happen-before t0's release
        if (t == 0) bar.fetch_add(1, cuda::memory_order_release);
    }

    // ---- outputs: h and c straight from owner registers ----
    if (t < 16) {
        out[1 + ((c << 4) + t)]   = hv;
        out[513 + ((c << 4) + t)] = cv;
    }

    // ---- CTA 0: final fc after the last barrier ----
    if (c == 0) {
        if (t == 0) {
            int guard = 0;
            while (bar.load(cuda::memory_order_acquire) < NCTA * TSTEPS) {
                if (++guard > SPIN_GUARD) break;
            }
        }
        __syncthreads();

        float hfin;
        {
            dev_atomic_f32 href(((float*)g_h[TSTEPS & 1])[t]);  // TSTEPS even -> buf 0
            hfin = href.load(cuda::memory_order_relaxed);
        }
        float p = hfin * fc_w[t];
        #pragma unroll
        for (int o = 16; o > 0; o >>= 1) p += __shfl_down_sync(0xffffffffu, p, o);
        if ((t & 31) == 0) red[t >> 5] = p;
        __syncthreads();
        if (t == 0) {
            float acc = fc_b[0];
            #pragma unroll
            for (int i = 0; i < 16; ++i) acc += red[i];
            out[0] = sigm(acc);
        }
    }
}

// ================= launch =================
extern "C" void kernel_launch(void* const* d_in, const int* in_sizes, int n_in,
                              void* d_out, int out_size)
{
    const int*   x     = (const int*)  d_in[0];
    const float* h0    = (const float*)d_in[1];
    const float* c0    = (const float*)d_in[2];
    const float* emb   = (const float*)d_in[3];
    const float* W_ih  = (const float*)d_in[4];
    const float* W_hh  = (const float*)d_in[5];
    const float* b_ih  = (const float*)d_in[6];
    const float* b_hh  = (const float*)d_in[7];
    const float* fc_w  = (const float*)d_in[8];
    const float* fc_b  = (const float*)d_in[9];
    float* out = (float*)d_out;

    dim3 pgrid(G4 / 16, (TSTEPS + 15) / 16);   // 128 x 19
    pre_kernel<<<pgrid, 256>>>(x, emb, W_ih, b_ih, b_hh, h0);
    lstm_persist<<<NCTA, TPB>>>(W_hh, c0, fc_w, fc_b, out);
}

// round 7
// speedup vs baseline: 2.4537x; 1.3406x over previous
#include <cuda_runtime.h>
#include <cuda/atomic>
#include <cstdint>

#define TSTEPS 300
#define HIDN   512
#define EMBD   300
#define G4     2048      // 4*HIDN
#define NCTA   32
#define TPB    512
#define SPIN_GUARD (1 << 20)

typedef unsigned long long u64;

// ---------------- scratch (static __device__, no allocs) ----------------
__device__ __align__(16) float g_pre[TSTEPS * G4]; // input-side gates (+biases)
__device__ __align__(16) u64   g_hw[2][HIDN];      // tagged hidden words: (tag<<32)|bits
                                                   // tag s = "h after s steps"

using dev_atomic_u64 = cuda::atomic_ref<u64, cuda::thread_scope_device>;

__device__ __forceinline__ u64 pack_h(float v, unsigned tag) {
    return ((u64)tag << 32) | (u64)__float_as_uint(v);
}

__device__ __forceinline__ float sigm(float x) { return 1.f / (1.f + __expf(-x)); }
__device__ __forceinline__ float tanh_f(float x) {
    // overflow-safe: tanh(x) = sign(x) * (1 - 2/(exp(2|x|)+1))
    float e = __expf(2.f * fabsf(x));
    float r = 1.f - 2.f / (e + 1.f);
    return copysignf(r, x);
}

// ================= Phase 1: pre[t][row] = W_ih @ emb[x[t]] + b_ih + b_hh ==========
// grid (128, 19), block 256.  Block covers 16 rows x 16 timesteps; K=300 loop.
__global__ void pre_kernel(const int* __restrict__ x,
                           const float* __restrict__ emb,
                           const float* __restrict__ W_ih,
                           const float* __restrict__ b_ih,
                           const float* __restrict__ b_hh,
                           const float* __restrict__ h0)
{
    __shared__ float E[16][301];   // stride 301 -> conflict-free column reads
    const int tB = blockIdx.y * 16;
    const int rB = blockIdx.x * 16;

    for (int idx = threadIdx.x; idx < 16 * EMBD; idx += 256) {
        int tt = idx / EMBD, k = idx % EMBD;
        int t = tB + tt;
        E[tt][k] = (t < TSTEPS) ? emb[(size_t)x[t] * EMBD + k] : 0.f;
    }
    __syncthreads();

    const int t_local = threadIdx.x & 15;
    const int r_local = threadIdx.x >> 4;
    const int r = rB + r_local;
    const int t = tB + t_local;

    const float* wr = W_ih + (size_t)r * EMBD;
    float a0 = 0.f, a1 = 0.f, a2 = 0.f, a3 = 0.f;
    #pragma unroll 4
    for (int k = 0; k < EMBD; k += 4) {
        a0 = fmaf(wr[k + 0], E[t_local][k + 0], a0);
        a1 = fmaf(wr[k + 1], E[t_local][k + 1], a1);
        a2 = fmaf(wr[k + 2], E[t_local][k + 2], a2);
        a3 = fmaf(wr[k + 3], E[t_local][k + 3], a3);
    }
    if (t < TSTEPS)
        g_pre[(size_t)t * G4 + r] = (a0 + a1) + (a2 + a3) + b_ih[r] + b_hh[r];

    // block (0,0): seed h words with tag 0 and poison the other buffer's tags
    // (kills any cross-replay tag collision; equality-compare polls can then
    //  never match a stale word)
    if (blockIdx.x == 0 && blockIdx.y == 0) {
        for (int i = threadIdx.x; i < HIDN; i += 256) {
            dev_atomic_u64 a0ref(g_hw[0][i]);
            dev_atomic_u64 a1ref(g_hw[1][i]);
            a0ref.store(pack_h(h0[i], 0u), cuda::memory_order_relaxed);
            a1ref.store(((u64)0xFFFFFFFFu << 32), cuda::memory_order_relaxed);
        }
    }
}

// ================= Phase 2: persistent recurrence, tagged-word sync =================
// 32 CTAs x 512 threads.  CTA c owns hidden units [16c,16c+16) -> 64 gate rows.
// Thread t: row rr = t>>3 (gate = rr>>4, unit = rr&15), h-chunk s = t&7 (64 MACs).
// W_hh slice lives in registers for all 300 steps.
// Sync: each h word carries its step tag; consumers poll their own word until
// tag == step.  Tag + payload share one atomic 64-bit word -> relaxed ordering
// suffices; no barrier, no fences on the critical path.
__global__ void __launch_bounds__(TPB, 1)
lstm_persist(const float* __restrict__ W_hh,
             const float* __restrict__ c0,
             const float* __restrict__ fc_w,
             const float* __restrict__ fc_b,
             float* __restrict__ out)
{
    const int c  = blockIdx.x;
    const int t  = threadIdx.x;
    const int rr = t >> 3;                 // 0..63
    const int s  = t & 7;                  // 0..7
    const int gate = rr >> 4;              // 0..3 (i,f,g,o)
    const int unit = (c << 4) + (rr & 15); // global hidden unit
    const int grow = gate * HIDN + unit;   // global gate row

    __shared__ __align__(16) float hs[8 * 68];  // 8 segments x 64 h-values, stride 68
    __shared__ float gsm[64];
    __shared__ float red[16];

    // ---- load W_hh slice into registers (kept for all 300 steps) ----
    float w[64];
    {
        const float4* wrow =
            reinterpret_cast<const float4*>(W_hh + (size_t)grow * HIDN + s * 64);
        #pragma unroll
        for (int i = 0; i < 16; ++i) {
            float4 v = wrow[i];
            w[4 * i + 0] = v.x; w[4 * i + 1] = v.y;
            w[4 * i + 2] = v.z; w[4 * i + 3] = v.w;
        }
    }

    float cv = 0.f, hv = 0.f;              // state for the 16 owner threads
    if (t < 16) cv = c0[(c << 4) + t];

    for (int step = 0; step < TSTEPS; ++step) {
        const int buf = step & 1;

        // independent of h: issue the input-side gate fetch before the poll so
        // it is in flight during the spin
        float prev = 0.f;
        if (s == 0) prev = __ldg(&g_pre[(size_t)step * G4 + grow]);

        // ---- poll own tagged word until tag == step; payload is h value ----
        {
            dev_atomic_u64 href(g_hw[buf][t]);
            u64 word;
            int guard = 0;
            do {
                word = href.load(cuda::memory_order_relaxed);
            } while ((unsigned)(word >> 32) != (unsigned)step &&
                     ++guard < SPIN_GUARD);
            hs[(t >> 6) * 68 + (t & 63)] = __uint_as_float((unsigned)word);
        }
        __syncthreads();                          // stage -> read

        // ---- 64-MAC partial dot: W in regs, h from conflict-free smem ----
        float a0 = 0.f, a1 = 0.f, a2 = 0.f, a3 = 0.f;
        const float4* hp4 = reinterpret_cast<const float4*>(&hs[s * 68]);
        #pragma unroll
        for (int i = 0; i < 16; ++i) {
            float4 h4 = hp4[i];
            a0 = fmaf(w[4 * i + 0], h4.x, a0);
            a1 = fmaf(w[4 * i + 1], h4.y, a1);
            a2 = fmaf(w[4 * i + 2], h4.z, a2);
            a3 = fmaf(w[4 * i + 3], h4.w, a3);
        }
        float part = (a0 + a1) + (a2 + a3);
        part += __shfl_down_sync(0xffffffffu, part, 4, 8);
        part += __shfl_down_sync(0xffffffffu, part, 2, 8);
        part += __shfl_down_sync(0xffffffffu, part, 1, 8);
        if (s == 0) gsm[rr] = part + prev;
        __syncthreads();                          // gsm write -> read; hs reads done

        // ---- cell update for the 16 owned units; publish tagged h ----
        if (t < 16) {
            float gi = gsm[t], gf = gsm[16 + t], gg = gsm[32 + t], go = gsm[48 + t];
            float i_ = sigm(gi);
            float f_ = sigm(gf);
            float g_ = tanh_f(gg);
            float o_ = sigm(go);
            float cn = fmaf(f_, cv, i_ * g_);
            cv = cn;
            hv = o_ * tanh_f(cn);
            dev_atomic_u64 hdst(g_hw[buf ^ 1][(c << 4) + t]);
            hdst.store(pack_h(hv, (unsigned)(step + 1)), cuda::memory_order_relaxed);
        }
        // no trailing sync needed: next iteration's hs writes are gated by the
        // per-thread poll, and the gsm rewrite is gated by the next sync
    }

    // ---- outputs: h and c straight from owner registers (off critical path) ----
    if (t < 16) {
        out[1 + ((c << 4) + t)]   = hv;
        out[513 + ((c << 4) + t)] = cv;
    }

    // ---- CTA 0: final fc once every word carries tag TSTEPS ----
    if (c == 0) {
        float hfin;
        {
            dev_atomic_u64 href(g_hw[TSTEPS & 1][t]);   // TSTEPS even -> buf 0
            u64 word;
            int guard = 0;
            do {
                word = href.load(cuda::memory_order_relaxed);
            } while ((unsigned)(word >> 32) != (unsigned)TSTEPS &&
                     ++guard < SPIN_GUARD);
            hfin = __uint_as_float((unsigned)word);
        }
        float p = hfin * fc_w[t];
        #pragma unroll
        for (int o = 16; o > 0; o >>= 1) p += __shfl_down_sync(0xffffffffu, p, o);
        if ((t & 31) == 0) red[t >> 5] = p;
        __syncthreads();
        if (t == 0) {
            float acc = fc_b[0];
            #pragma unroll
            for (int i = 0; i < 16; ++i) acc += red[i];
            out[0] = sigm(acc);
        }
    }
}

// ================= launch =================
extern "C" void kernel_launch(void* const* d_in, const int* in_sizes, int n_in,
                              void* d_out, int out_size)
{
    const int*   x     = (const int*)  d_in[0];
    const float* h0    = (const float*)d_in[1];
    const float* c0    = (const float*)d_in[2];
    const float* emb   = (const float*)d_in[3];
    const float* W_ih  = (const float*)d_in[4];
    const float* W_hh  = (const float*)d_in[5];
    const float* b_ih  = (const float*)d_in[6];
    const float* b_hh  = (const float*)d_in[7];
    const float* fc_w  = (const float*)d_in[8];
    const float* fc_b  = (const float*)d_in[9];
    float* out = (float*)d_out;

    dim3 pgrid(G4 / 16, (TSTEPS + 15) / 16);   // 128 x 19
    pre_kernel<<<pgrid, 256>>>(x, emb, W_ih, b_ih, b_hh, h0);
    lstm_persist<<<NCTA, TPB>>>(W_hh, c0, fc_w, fc_b, out);
}